// round 12
// baseline (speedup 1.0000x reference)
#include <cuda_runtime.h>
#include <math.h>

#define Hh 160
#define Ww 480
#define HW 76800
#define NP 120000

// ---------------- scratch (no allocations allowed) ----------------
__device__ __align__(16) int    d_win[3][HW];
__device__ __align__(16) float4 d_G0[9][16];    // folded red_w0 -> tap weights [k][c/4]
__device__ __align__(16) float4 d_G1[9][32];    // folded red_w1 -> tap weights
__device__ __align__(16) float4 d_Wpt[9][64];   // sb_w[256:512] transposed to [k][o/4]
__device__ __align__(16) float4 d_Wb[768];      // img tap weights, [c][12] padded rows
__device__ float  d_cb[9];                      // folded bias constants per tap
__device__ __align__(16) float  d_ti[9][HW];    // image-part tap maps (incl cb)
__device__ __align__(16) float  d_tp[9][HW];    // voxel tap maps (REDG-accumulated)

// ---------------- K0: prep (blocks 0..8) + init (blocks 9..683) --------------
__global__ void k_initprep(const float* __restrict__ rw0, const float* __restrict__ rb0,
                           const float* __restrict__ rw1, const float* __restrict__ rb1,
                           const float* __restrict__ sbw) {
    int b = blockIdx.x;
    int tid = threadIdx.x;
    if (b < 9) {
        int k = b;
        ((float*)d_Wb)[tid * 12 + k] = sbw[tid * 9 + k];           // img weights, padded rows
        ((float*)d_Wpt)[k * 256 + tid] = sbw[(256 + tid) * 9 + k];
        if (tid < 64) {
            float s = 0.f;
            for (int o = 0; o < 256; o++) s += rw0[o * 64 + tid] * sbw[(256 + o) * 9 + k];
            ((float*)d_G0)[k * 64 + tid] = s;
        }
        if (tid < 128) {
            float s = 0.f;
            for (int o = 0; o < 256; o++) s += rw1[o * 128 + tid] * sbw[(256 + o) * 9 + k];
            ((float*)d_G1)[k * 128 + tid] = s;
        }
        if (tid == 0) {
            float s = 0.f;
            for (int o = 0; o < 256; o++) s += (rb0[o] + rb1[o]) * sbw[(256 + o) * 9 + k];
            d_cb[k] = s;
        }
    } else {
        int i = (b - 9) * 256 + tid;          // 0 .. 172799 float4 over d_tp
        ((float4*)d_tp)[i] = make_float4(0.f, 0.f, 0.f, 0.f);
        if (i < 3 * HW / 4) ((int4*)d_win)[i] = make_int4(-1, -1, -1, -1);
    }
}

// ---------------- K1: scatter, last-write-wins == max point index ------------
__global__ void k_scatter(const int* __restrict__ g0, const int* __restrict__ g1,
                          const int* __restrict__ g2) {
    int i = blockIdx.x * blockDim.x + threadIdx.x;
    if (i >= 3 * NP) return;
    int lvl = i / NP;
    int p = i - lvl * NP;
    const int* g = (lvl == 0) ? g0 : ((lvl == 1) ? g1 : g2);
    int2 xy = ((const int2*)g)[p];
    if (xy.x >= 0 && xy.x < Ww && xy.y >= 0 && xy.y < Hh)
        atomicMax(&d_win[lvl][xy.y * Ww + xy.x], p);
}

// ---------------- voxel part: in-smem compaction + gather + REDG (R8 form) ---
template <int LVL, int C4>
__device__ __forceinline__ void voxel_body(const float* __restrict__ vf,
                                           float4* sw, int2* s_lst, int* s_w,
                                           int blk) {
    int tid = threadIdx.x;
    const float4* wsrc = (LVL == 0) ? (const float4*)d_G0
                        : (LVL == 1) ? (const float4*)d_G1
                                     : (const float4*)d_Wpt;
    for (int i = tid; i < 9 * C4; i += 256) sw[i] = wsrc[i];

    // local compaction of this block's 256 cells
    int cell = blk * 256 + tid;
    int p = d_win[LVL][cell];
    bool v = p >= 0;
    unsigned m = __ballot_sync(0xffffffffu, v);
    int lane = tid & 31;
    int w    = tid >> 5;
    if (lane == 0) s_w[w] = __popc(m);
    __syncthreads();
    if (tid == 0) {
        int t = 0;
#pragma unroll
        for (int i = 0; i < 8; i++) { int c = s_w[i]; s_w[i] = t; t += c; }
        s_w[8] = t;
    }
    __syncthreads();
    if (v) {
        int pos = s_w[w] + __popc(m & ((1u << lane) - 1));
        s_lst[pos] = make_int2(cell, p);
    }
    __syncthreads();
    int n = s_w[8];

    int sub = lane >> 3;   // slot within warp (0..3)
    int cs  = lane & 7;    // channel lane (0..7)

    for (int base = 0; base < n; base += 64) {
        int i0 = base + w * 8 + sub * 2;
        int i1 = i0 + 1;
        bool ok0 = i0 < n;
        bool ok1 = i1 < n;
        int2 e0 = ok0 ? s_lst[i0] : make_int2(0, 0);
        int2 e1 = ok1 ? s_lst[i1] : make_int2(0, 0);
        const float4* rowA = (const float4*)vf + (size_t)e0.y * C4;
        const float4* rowB = (const float4*)vf + (size_t)e1.y * C4;

        float accA[9], accB[9];
#pragma unroll
        for (int k = 0; k < 9; k++) { accA[k] = 0.f; accB[k] = 0.f; }

#pragma unroll 2
        for (int mm = 0; mm < C4 / 8; mm++) {
            int c4 = cs + 8 * mm;
            float4 va = rowA[c4];
            float4 vb = rowB[c4];
#pragma unroll
            for (int k = 0; k < 9; k++) {
                float4 wv = sw[k * C4 + c4];
                accA[k] += va.x * wv.x + va.y * wv.y + va.z * wv.z + va.w * wv.w;
                accB[k] += vb.x * wv.x + vb.y * wv.y + vb.z * wv.z + vb.w * wv.w;
            }
        }
#pragma unroll
        for (int k = 0; k < 9; k++) {
            float sA = accA[k];
            float sB = accB[k];
            sA += __shfl_xor_sync(0xffffffffu, sA, 1);
            sB += __shfl_xor_sync(0xffffffffu, sB, 1);
            sA += __shfl_xor_sync(0xffffffffu, sA, 2);
            sB += __shfl_xor_sync(0xffffffffu, sB, 2);
            sA += __shfl_xor_sync(0xffffffffu, sA, 4);
            sB += __shfl_xor_sync(0xffffffffu, sB, 4);
            if (cs == 0) {
                if (ok0) atomicAdd(&d_tp[k][e0.x], sA);   // REDG.F32, no return
                if (ok1) atomicAdd(&d_tp[k][e1.x], sB);
            }
        }
    }
}

// ---------------- K2: voxel kernel (900 blocks, interleaved levels) -----------
__global__ void __launch_bounds__(256, 4) k_vox(const float* __restrict__ vf0,
                                                const float* __restrict__ vf1,
                                                const float* __restrict__ vf2) {
    __shared__ __align__(16) float swf[2304];   // 9KB weight buffer (max 9*64 float4)
    __shared__ __align__(16) int2 s_lst[256];
    __shared__ int s_w[9];
    int b = blockIdx.x;
    int type = b % 3;
    int sb = b / 3;
    if (type == 0)      voxel_body<2, 64>(vf2, (float4*)swf, s_lst, s_w, sb);
    else if (type == 1) voxel_body<1, 32>(vf1, (float4*)swf, s_lst, s_w, sb);
    else                voxel_body<0, 16>(vf0, (float4*)swf, s_lst, s_w, sb);
}

// ---------------- K3: image kernel — 600 blocks x 128 px, one wave ------------
// warp = 4 quad-slots x 8 channel-lanes; thread: 32 iters, 36-reg acc
__global__ void __launch_bounds__(256, 4) k_img(const float* __restrict__ img,
                                                const float* __restrict__ seg) {
    __shared__ __align__(16) float sWf[9216];   // 768 float4 = [c][12] padded rows
    __shared__ float scb[9];
    int tid = threadIdx.x;
    for (int i = tid; i < 768; i += 256) ((float4*)sWf)[i] = d_Wb[i];
    if (tid < 9) scb[tid] = d_cb[tid];
    __syncthreads();

    int lane = tid & 31;
    int w    = tid >> 5;
    int cs   = lane & 7;    // channel lane (0..7)
    int sub  = lane >> 3;   // quad slot (0..3)
    int px   = blockIdx.x * 128 + w * 16 + sub * 4;

    float4 acc[9];
#pragma unroll
    for (int k = 0; k < 9; k++) acc[k] = make_float4(0.f, 0.f, 0.f, 0.f);

#pragma unroll 4
    for (int m = 0; m < 32; m++) {
        int c = cs + 8 * m;
        float4 v = *(const float4*)(img + (size_t)c * HW + px);
        const float* wp = sWf + c * 12;
        float4 w0 = *(const float4*)wp;
        float4 w1 = *(const float4*)(wp + 4);
        float  w8 = wp[8];
        acc[0].x += v.x * w0.x; acc[0].y += v.y * w0.x; acc[0].z += v.z * w0.x; acc[0].w += v.w * w0.x;
        acc[1].x += v.x * w0.y; acc[1].y += v.y * w0.y; acc[1].z += v.z * w0.y; acc[1].w += v.w * w0.y;
        acc[2].x += v.x * w0.z; acc[2].y += v.y * w0.z; acc[2].z += v.z * w0.z; acc[2].w += v.w * w0.z;
        acc[3].x += v.x * w0.w; acc[3].y += v.y * w0.w; acc[3].z += v.z * w0.w; acc[3].w += v.w * w0.w;
        acc[4].x += v.x * w1.x; acc[4].y += v.y * w1.x; acc[4].z += v.z * w1.x; acc[4].w += v.w * w1.x;
        acc[5].x += v.x * w1.y; acc[5].y += v.y * w1.y; acc[5].z += v.z * w1.y; acc[5].w += v.w * w1.y;
        acc[6].x += v.x * w1.z; acc[6].y += v.y * w1.z; acc[6].z += v.z * w1.z; acc[6].w += v.w * w1.z;
        acc[7].x += v.x * w1.w; acc[7].y += v.y * w1.w; acc[7].z += v.z * w1.w; acc[7].w += v.w * w1.w;
        acc[8].x += v.x * w8;   acc[8].y += v.y * w8;   acc[8].z += v.z * w8;   acc[8].w += v.w * w8;
    }

    // reduce across the 8 channel-lanes (xor 1, 2, 4)
#pragma unroll
    for (int k = 0; k < 9; k++) {
        acc[k].x += __shfl_xor_sync(0xffffffffu, acc[k].x, 1);
        acc[k].y += __shfl_xor_sync(0xffffffffu, acc[k].y, 1);
        acc[k].z += __shfl_xor_sync(0xffffffffu, acc[k].z, 1);
        acc[k].w += __shfl_xor_sync(0xffffffffu, acc[k].w, 1);
        acc[k].x += __shfl_xor_sync(0xffffffffu, acc[k].x, 2);
        acc[k].y += __shfl_xor_sync(0xffffffffu, acc[k].y, 2);
        acc[k].z += __shfl_xor_sync(0xffffffffu, acc[k].z, 2);
        acc[k].w += __shfl_xor_sync(0xffffffffu, acc[k].w, 2);
        acc[k].x += __shfl_xor_sync(0xffffffffu, acc[k].x, 4);
        acc[k].y += __shfl_xor_sync(0xffffffffu, acc[k].y, 4);
        acc[k].z += __shfl_xor_sync(0xffffffffu, acc[k].z, 4);
        acc[k].w += __shfl_xor_sync(0xffffffffu, acc[k].w, 4);
    }
    if (cs == 0) {
        float4 sg = *(const float4*)(seg + HW + px);
#pragma unroll
        for (int k = 0; k < 9; k++) {
            float4 o;
            o.x = scb[k] + sg.x * acc[k].x;
            o.y = scb[k] + sg.y * acc[k].y;
            o.z = scb[k] + sg.z * acc[k].z;
            o.w = scb[k] + sg.w * acc[k].w;
            *(float4*)(&d_ti[k][px]) = o;
        }
    }
}

// ---------------- K4: att (128 px into smem) + gated output stream ------------
__global__ void __launch_bounds__(256) k_attout(const float* __restrict__ img,
                                                const float* __restrict__ seg,
                                                const float* __restrict__ sbb,
                                                float* __restrict__ out) {
    __shared__ __align__(16) float satt[128];
    int tid = threadIdx.x;
    int base = blockIdx.x * 128;
    if (tid < 128) {
        int pix = base + tid;
        int y = pix / Ww;
        int x = pix - y * Ww;
        float sum = sbb[0];
#pragma unroll
        for (int ky = 0; ky < 3; ky++) {
            int yy = y + ky - 1;
            if (yy < 0 || yy >= Hh) continue;
#pragma unroll
            for (int kx = 0; kx < 3; kx++) {
                int xx = x + kx - 1;
                if (xx < 0 || xx >= Ww) continue;
                int kk = ky * 3 + kx;
                int ni = yy * Ww + xx;
                sum += d_ti[kk][ni] + d_tp[kk][ni];
            }
        }
        float att = 1.f / (1.f + expf(-sum));
        satt[tid] = att * seg[HW + pix];
    }
    __syncthreads();

    // stream all 256 channels for this block's 128 pixels (32 float4 per channel)
    int q = tid & 31;          // pixel-quad within block (0..31)
    int c0 = tid >> 5;         // starting channel (0..7)
    float4 a = ((const float4*)satt)[q];
    const float4* im4 = (const float4*)img;
    float4* o4 = (float4*)out;
    size_t idx = (size_t)c0 * (HW / 4) + (base / 4) + q;
#pragma unroll 8
    for (int c = c0; c < 256; c += 8, idx += (size_t)8 * (HW / 4)) {
        float4 v = im4[idx];
        v.x *= a.x; v.y *= a.y; v.z *= a.z; v.w *= a.w;
        o4[idx] = v;
    }
}

extern "C" void kernel_launch(void* const* d_in, const int* in_sizes, int n_in,
                              void* d_out, int out_size) {
    const float* img = (const float*)d_in[0];
    const float* seg = (const float*)d_in[1];

    int iv0, iv1, iv2, ig0, ig1, ig2;
    if (in_sizes[3] == 2 * NP) { iv0 = 2; ig0 = 3; iv1 = 4; ig1 = 5; iv2 = 6; ig2 = 7; }
    else                       { iv0 = 2; iv1 = 3; iv2 = 4; ig0 = 5; ig1 = 6; ig2 = 7; }

    const float* vf0 = (const float*)d_in[iv0];
    const float* vf1 = (const float*)d_in[iv1];
    const float* vf2 = (const float*)d_in[iv2];
    const int*   g0  = (const int*)d_in[ig0];
    const int*   g1  = (const int*)d_in[ig1];
    const int*   g2  = (const int*)d_in[ig2];
    const float* rw0 = (const float*)d_in[8];
    const float* rb0 = (const float*)d_in[9];
    const float* rw1 = (const float*)d_in[10];
    const float* rb1 = (const float*)d_in[11];
    const float* sbw = (const float*)d_in[12];
    const float* sbb = (const float*)d_in[13];

    k_initprep<<<684, 256>>>(rw0, rb0, rw1, rb1, sbw);
    k_scatter<<<(3 * NP + 255) / 256, 256>>>(g0, g1, g2);
    k_vox<<<900, 256>>>(vf0, vf1, vf2);
    k_img<<<600, 256>>>(img, seg);
    k_attout<<<HW / 128, 256>>>(img, seg, sbb, (float*)d_out);
}

// round 13
// speedup vs baseline: 1.0876x; 1.0876x over previous
#include <cuda_runtime.h>
#include <math.h>

#define Hh 160
#define Ww 480
#define HW 76800
#define NP 120000

// ---------------- scratch (no allocations allowed) ----------------
__device__ __align__(16) int    d_win[3][HW];
__device__ __align__(16) float4 d_G0[9][16];    // folded red_w0 -> tap weights [k][c/4]
__device__ __align__(16) float4 d_G1[9][32];    // folded red_w1 -> tap weights
__device__ __align__(16) float4 d_Wpt[9][64];   // sb_w[256:512] transposed to [k][o/4]
__device__ __align__(16) float4 d_Wb[768];      // img tap weights, [c][12] padded rows
__device__ float  d_cb[9];                      // folded bias constants per tap
__device__ __align__(16) float  d_ti[9][HW];    // image-part tap maps (incl cb)
__device__ __align__(16) float  d_tp[9][HW];    // voxel tap maps (REDG-accumulated)

// ---------------- K0: prep (blocks 0..8) + init (blocks 9..683) --------------
__global__ void k_initprep(const float* __restrict__ rw0, const float* __restrict__ rb0,
                           const float* __restrict__ rw1, const float* __restrict__ rb1,
                           const float* __restrict__ sbw) {
    int b = blockIdx.x;
    int tid = threadIdx.x;
    if (b < 9) {
        int k = b;
        ((float*)d_Wb)[tid * 12 + k] = sbw[tid * 9 + k];           // img weights, padded rows
        ((float*)d_Wpt)[k * 256 + tid] = sbw[(256 + tid) * 9 + k];
        if (tid < 64) {
            float s = 0.f;
            for (int o = 0; o < 256; o++) s += rw0[o * 64 + tid] * sbw[(256 + o) * 9 + k];
            ((float*)d_G0)[k * 64 + tid] = s;
        }
        if (tid < 128) {
            float s = 0.f;
            for (int o = 0; o < 256; o++) s += rw1[o * 128 + tid] * sbw[(256 + o) * 9 + k];
            ((float*)d_G1)[k * 128 + tid] = s;
        }
        if (tid == 0) {
            float s = 0.f;
            for (int o = 0; o < 256; o++) s += (rb0[o] + rb1[o]) * sbw[(256 + o) * 9 + k];
            d_cb[k] = s;
        }
    } else {
        int i = (b - 9) * 256 + tid;          // 0 .. 172799 float4 over d_tp
        ((float4*)d_tp)[i] = make_float4(0.f, 0.f, 0.f, 0.f);
        if (i < 3 * HW / 4) ((int4*)d_win)[i] = make_int4(-1, -1, -1, -1);
    }
}

// ---------------- K1: scatter, last-write-wins == max point index ------------
__global__ void k_scatter(const int* __restrict__ g0, const int* __restrict__ g1,
                          const int* __restrict__ g2) {
    int i = blockIdx.x * blockDim.x + threadIdx.x;
    if (i >= 3 * NP) return;
    int lvl = i / NP;
    int p = i - lvl * NP;
    const int* g = (lvl == 0) ? g0 : ((lvl == 1) ? g1 : g2);
    int2 xy = ((const int2*)g)[p];
    if (xy.x >= 0 && xy.x < Ww && xy.y >= 0 && xy.y < Hh)
        atomicMax(&d_win[lvl][xy.y * Ww + xy.x], p);
}

// ---------------- img part: channel-uniform warp layout ----------------------
// warp = 1 channel x 128 px per iter (512B contiguous LDG, broadcast LDS);
// warp w covers channels [32w, 32w+32); cross-warp combine via s_part.
__device__ __forceinline__ void img_body(const float* __restrict__ img,
                                         const float* __restrict__ seg,
                                         float* smem, int blk) {
    float* sWf    = smem;           // 3072 floats: [c][12] padded weight rows
    float* s_part = smem + 3072;    // 8*9*128 floats: per-warp partials

    int tid = threadIdx.x;
    for (int i = tid; i < 768; i += 256) ((float4*)sWf)[i] = d_Wb[i];
    __syncthreads();

    int lane = tid & 31;
    int w    = tid >> 5;
    int px0  = blk * 128;
    int px   = px0 + lane * 4;

    float4 acc[9];
#pragma unroll
    for (int k = 0; k < 9; k++) acc[k] = make_float4(0.f, 0.f, 0.f, 0.f);

#pragma unroll 2
    for (int m = 0; m < 32; m++) {
        int c = w * 32 + m;
        float4 v = *(const float4*)(img + (size_t)c * HW + px);
        const float* wp = sWf + c * 12;
        float4 w0 = *(const float4*)wp;        // broadcast LDS
        float4 w1 = *(const float4*)(wp + 4);
        float  w8 = wp[8];
        acc[0].x += v.x * w0.x; acc[0].y += v.y * w0.x; acc[0].z += v.z * w0.x; acc[0].w += v.w * w0.x;
        acc[1].x += v.x * w0.y; acc[1].y += v.y * w0.y; acc[1].z += v.z * w0.y; acc[1].w += v.w * w0.y;
        acc[2].x += v.x * w0.z; acc[2].y += v.y * w0.z; acc[2].z += v.z * w0.z; acc[2].w += v.w * w0.z;
        acc[3].x += v.x * w0.w; acc[3].y += v.y * w0.w; acc[3].z += v.z * w0.w; acc[3].w += v.w * w0.w;
        acc[4].x += v.x * w1.x; acc[4].y += v.y * w1.x; acc[4].z += v.z * w1.x; acc[4].w += v.w * w1.x;
        acc[5].x += v.x * w1.y; acc[5].y += v.y * w1.y; acc[5].z += v.z * w1.y; acc[5].w += v.w * w1.y;
        acc[6].x += v.x * w1.z; acc[6].y += v.y * w1.z; acc[6].z += v.z * w1.z; acc[6].w += v.w * w1.z;
        acc[7].x += v.x * w1.w; acc[7].y += v.y * w1.w; acc[7].z += v.z * w1.w; acc[7].w += v.w * w1.w;
        acc[8].x += v.x * w8;   acc[8].y += v.y * w8;   acc[8].z += v.z * w8;   acc[8].w += v.w * w8;
    }

    // stage partials: warp w writes its [9][128] slice (conflict-free STS.128)
#pragma unroll
    for (int k = 0; k < 9; k++)
        *(float4*)(s_part + (w * 9 + k) * 128 + lane * 4) = acc[k];
    __syncthreads();

    // reduce over 8 warps + apply seg gate + bias, store d_ti
    for (int i = tid; i < 288; i += 256) {     // 288 = 9 taps * 32 px-quads
        int k = i / 32;
        int q = i - k * 32;
        float4 s = make_float4(0.f, 0.f, 0.f, 0.f);
#pragma unroll
        for (int ww = 0; ww < 8; ww++) {
            float4 t = *(const float4*)(s_part + (ww * 9 + k) * 128 + q * 4);
            s.x += t.x; s.y += t.y; s.z += t.z; s.w += t.w;
        }
        float cb = d_cb[k];
        float4 sg = *(const float4*)(seg + HW + px0 + q * 4);
        float4 o;
        o.x = cb + sg.x * s.x;
        o.y = cb + sg.y * s.y;
        o.z = cb + sg.z * s.z;
        o.w = cb + sg.w * s.w;
        *(float4*)(&d_ti[k][px0 + q * 4]) = o;
    }
}

// ---------------- voxel part: in-smem compaction + gather + REDG (R8 form) ---
template <int LVL, int C4>
__device__ __forceinline__ void voxel_body(const float* __restrict__ vf,
                                           float* smem, int blk) {
    float4* sw   = (float4*)smem;               // 9*C4 float4
    int2* s_lst  = (int2*)(smem + 2304);        // 256 int2
    int* s_w     = (int*)(smem + 2816);         // 9 ints

    int tid = threadIdx.x;
    const float4* wsrc = (LVL == 0) ? (const float4*)d_G0
                        : (LVL == 1) ? (const float4*)d_G1
                                     : (const float4*)d_Wpt;
    for (int i = tid; i < 9 * C4; i += 256) sw[i] = wsrc[i];

    // local compaction of this block's 256 cells
    int cell = blk * 256 + tid;
    int p = d_win[LVL][cell];
    bool v = p >= 0;
    unsigned m = __ballot_sync(0xffffffffu, v);
    int lane = tid & 31;
    int w    = tid >> 5;
    if (lane == 0) s_w[w] = __popc(m);
    __syncthreads();
    if (tid == 0) {
        int t = 0;
#pragma unroll
        for (int i = 0; i < 8; i++) { int c = s_w[i]; s_w[i] = t; t += c; }
        s_w[8] = t;
    }
    __syncthreads();
    if (v) {
        int pos = s_w[w] + __popc(m & ((1u << lane) - 1));
        s_lst[pos] = make_int2(cell, p);
    }
    __syncthreads();
    int n = s_w[8];

    int sub = lane >> 3;   // slot within warp (0..3)
    int cs  = lane & 7;    // channel lane (0..7)

    for (int base = 0; base < n; base += 64) {
        int i0 = base + w * 8 + sub * 2;
        int i1 = i0 + 1;
        bool ok0 = i0 < n;
        bool ok1 = i1 < n;
        int2 e0 = ok0 ? s_lst[i0] : make_int2(0, 0);
        int2 e1 = ok1 ? s_lst[i1] : make_int2(0, 0);
        const float4* rowA = (const float4*)vf + (size_t)e0.y * C4;
        const float4* rowB = (const float4*)vf + (size_t)e1.y * C4;

        float accA[9], accB[9];
#pragma unroll
        for (int k = 0; k < 9; k++) { accA[k] = 0.f; accB[k] = 0.f; }

#pragma unroll 2
        for (int mm = 0; mm < C4 / 8; mm++) {
            int c4 = cs + 8 * mm;
            float4 va = rowA[c4];
            float4 vb = rowB[c4];
#pragma unroll
            for (int k = 0; k < 9; k++) {
                float4 wv = sw[k * C4 + c4];
                accA[k] += va.x * wv.x + va.y * wv.y + va.z * wv.z + va.w * wv.w;
                accB[k] += vb.x * wv.x + vb.y * wv.y + vb.z * wv.z + vb.w * wv.w;
            }
        }
#pragma unroll
        for (int k = 0; k < 9; k++) {
            float sA = accA[k];
            float sB = accB[k];
            sA += __shfl_xor_sync(0xffffffffu, sA, 1);
            sB += __shfl_xor_sync(0xffffffffu, sB, 1);
            sA += __shfl_xor_sync(0xffffffffu, sA, 2);
            sB += __shfl_xor_sync(0xffffffffu, sB, 2);
            sA += __shfl_xor_sync(0xffffffffu, sA, 4);
            sB += __shfl_xor_sync(0xffffffffu, sB, 4);
            if (cs == 0) {
                if (ok0) atomicAdd(&d_tp[k][e0.x], sA);   // REDG.F32, no return
                if (ok1) atomicAdd(&d_tp[k][e1.x], sB);
            }
        }
    }
}

// ---------------- K2: fused work kernel, 900 vox + 600 img interleaved 3:2 ----
// b%5: {0:vox2, 1:img, 2:vox1, 3:img, 4:vox0}; 1500 blocks total
__global__ void __launch_bounds__(256, 4) k_work(const float* __restrict__ img,
                                                 const float* __restrict__ seg,
                                                 const float* __restrict__ vf0,
                                                 const float* __restrict__ vf1,
                                                 const float* __restrict__ vf2) {
    __shared__ __align__(16) float smem[12288];   // 48KB union (img: 3072+9216)
    int b = blockIdx.x;
    int type = b % 5;
    int g5 = b / 5;                               // 0..299
    if (type == 0)      voxel_body<2, 64>(vf2, smem, g5);
    else if (type == 2) voxel_body<1, 32>(vf1, smem, g5);
    else if (type == 4) voxel_body<0, 16>(vf0, smem, g5);
    else                img_body(img, seg, smem, g5 * 2 + (type == 3));
}

// ---------------- K3: att (128 px into smem) + gated output stream ------------
__global__ void __launch_bounds__(256) k_attout(const float* __restrict__ img,
                                                const float* __restrict__ seg,
                                                const float* __restrict__ sbb,
                                                float* __restrict__ out) {
    __shared__ __align__(16) float satt[128];
    int tid = threadIdx.x;
    int base = blockIdx.x * 128;
    if (tid < 128) {
        int pix = base + tid;
        int y = pix / Ww;
        int x = pix - y * Ww;
        float sum = sbb[0];
#pragma unroll
        for (int ky = 0; ky < 3; ky++) {
            int yy = y + ky - 1;
            if (yy < 0 || yy >= Hh) continue;
#pragma unroll
            for (int kx = 0; kx < 3; kx++) {
                int xx = x + kx - 1;
                if (xx < 0 || xx >= Ww) continue;
                int kk = ky * 3 + kx;
                int ni = yy * Ww + xx;
                sum += d_ti[kk][ni] + d_tp[kk][ni];
            }
        }
        float att = 1.f / (1.f + expf(-sum));
        satt[tid] = att * seg[HW + pix];
    }
    __syncthreads();

    // stream all 256 channels for this block's 128 pixels (32 float4 per channel)
    int q = tid & 31;          // pixel-quad within block (0..31)
    int c0 = tid >> 5;         // starting channel (0..7)
    float4 a = ((const float4*)satt)[q];
    const float4* im4 = (const float4*)img;
    float4* o4 = (float4*)out;
    size_t idx = (size_t)c0 * (HW / 4) + (base / 4) + q;
#pragma unroll 8
    for (int c = c0; c < 256; c += 8, idx += (size_t)8 * (HW / 4)) {
        float4 v = im4[idx];
        v.x *= a.x; v.y *= a.y; v.z *= a.z; v.w *= a.w;
        o4[idx] = v;
    }
}

extern "C" void kernel_launch(void* const* d_in, const int* in_sizes, int n_in,
                              void* d_out, int out_size) {
    const float* img = (const float*)d_in[0];
    const float* seg = (const float*)d_in[1];

    int iv0, iv1, iv2, ig0, ig1, ig2;
    if (in_sizes[3] == 2 * NP) { iv0 = 2; ig0 = 3; iv1 = 4; ig1 = 5; iv2 = 6; ig2 = 7; }
    else                       { iv0 = 2; iv1 = 3; iv2 = 4; ig0 = 5; ig1 = 6; ig2 = 7; }

    const float* vf0 = (const float*)d_in[iv0];
    const float* vf1 = (const float*)d_in[iv1];
    const float* vf2 = (const float*)d_in[iv2];
    const int*   g0  = (const int*)d_in[ig0];
    const int*   g1  = (const int*)d_in[ig1];
    const int*   g2  = (const int*)d_in[ig2];
    const float* rw0 = (const float*)d_in[8];
    const float* rb0 = (const float*)d_in[9];
    const float* rw1 = (const float*)d_in[10];
    const float* rb1 = (const float*)d_in[11];
    const float* sbw = (const float*)d_in[12];
    const float* sbb = (const float*)d_in[13];

    k_initprep<<<684, 256>>>(rw0, rb0, rw1, rb1, sbw);
    k_scatter<<<(3 * NP + 255) / 256, 256>>>(g0, g1, g2);
    k_work<<<1500, 256>>>(img, seg, vf0, vf1, vf2);
    k_attout<<<HW / 128, 256>>>(img, seg, sbb, (float*)d_out);
}

// round 16
// speedup vs baseline: 1.0878x; 1.0002x over previous
#include <cuda_runtime.h>
#include <math.h>

#define Hh 160
#define Ww 480
#define HW 76800
#define NP 120000

// ---------------- scratch (no allocations allowed) ----------------
__device__ __align__(16) int    d_win[3][HW];
__device__ __align__(16) float4 d_G0[9][16];    // folded red_w0 -> tap weights [k][c/4]
__device__ __align__(16) float4 d_G1[9][32];    // folded red_w1 -> tap weights
__device__ __align__(16) float4 d_Wpt[9][64];   // sb_w[256:512] transposed to [k][o/4]
__device__ __align__(16) float4 d_Wb[768];      // img tap weights, [c][12] padded rows
__device__ float  d_cb[9];                      // folded bias constants per tap
__device__ __align__(16) float  d_ti[9][HW];    // image-part tap maps (incl cb)
__device__ __align__(16) float  d_tp[9][HW];    // voxel tap maps (REDG-accumulated)

// ---------------- K0: prep (blocks 0..8) + init (blocks 9..683) --------------
__global__ void k_initprep(const float* __restrict__ rw0, const float* __restrict__ rb0,
                           const float* __restrict__ rw1, const float* __restrict__ rb1,
                           const float* __restrict__ sbw) {
    int b = blockIdx.x;
    int tid = threadIdx.x;
    if (b < 9) {
        int k = b;
        ((float*)d_Wb)[tid * 12 + k] = sbw[tid * 9 + k];           // img weights, padded rows
        ((float*)d_Wpt)[k * 256 + tid] = sbw[(256 + tid) * 9 + k];
        if (tid < 64) {
            float s = 0.f;
            for (int o = 0; o < 256; o++) s += rw0[o * 64 + tid] * sbw[(256 + o) * 9 + k];
            ((float*)d_G0)[k * 64 + tid] = s;
        }
        if (tid < 128) {
            float s = 0.f;
            for (int o = 0; o < 256; o++) s += rw1[o * 128 + tid] * sbw[(256 + o) * 9 + k];
            ((float*)d_G1)[k * 128 + tid] = s;
        }
        if (tid == 0) {
            float s = 0.f;
            for (int o = 0; o < 256; o++) s += (rb0[o] + rb1[o]) * sbw[(256 + o) * 9 + k];
            d_cb[k] = s;
        }
    } else {
        int i = (b - 9) * 256 + tid;          // 0 .. 172799 float4 over d_tp
        ((float4*)d_tp)[i] = make_float4(0.f, 0.f, 0.f, 0.f);
        if (i < 3 * HW / 4) ((int4*)d_win)[i] = make_int4(-1, -1, -1, -1);
    }
}

// ---------------- K1: scatter, last-write-wins == max point index ------------
__global__ void k_scatter(const int* __restrict__ g0, const int* __restrict__ g1,
                          const int* __restrict__ g2) {
    int i = blockIdx.x * blockDim.x + threadIdx.x;
    if (i >= 3 * NP) return;
    int lvl = i / NP;
    int p = i - lvl * NP;
    const int* g = (lvl == 0) ? g0 : ((lvl == 1) ? g1 : g2);
    int2 xy = ((const int2*)g)[p];
    if (xy.x >= 0 && xy.x < Ww && xy.y >= 0 && xy.y < Hh)
        atomicMax(&d_win[lvl][xy.y * Ww + xy.x], p);
}

// ---------------- img part: channel-uniform warp layout ----------------------
// warp = 1 channel x 128 px per iter (512B contiguous LDG, broadcast LDS);
// warp w covers channels [32w, 32w+32); cross-warp combine via s_part.
__device__ __forceinline__ void img_body(const float* __restrict__ img,
                                         const float* __restrict__ seg,
                                         float* smem, int blk) {
    float* sWf    = smem;           // 3072 floats: [c][12] padded weight rows
    float* s_part = smem + 3072;    // 8*9*128 floats: per-warp partials

    int tid = threadIdx.x;
    for (int i = tid; i < 768; i += 256) ((float4*)sWf)[i] = d_Wb[i];
    __syncthreads();

    int lane = tid & 31;
    int w    = tid >> 5;
    int px0  = blk * 128;
    int px   = px0 + lane * 4;

    float4 acc[9];
#pragma unroll
    for (int k = 0; k < 9; k++) acc[k] = make_float4(0.f, 0.f, 0.f, 0.f);

#pragma unroll 2
    for (int m = 0; m < 32; m++) {
        int c = w * 32 + m;
        float4 v = *(const float4*)(img + (size_t)c * HW + px);
        const float* wp = sWf + c * 12;
        float4 w0 = *(const float4*)wp;        // broadcast LDS
        float4 w1 = *(const float4*)(wp + 4);
        float  w8 = wp[8];
        acc[0].x += v.x * w0.x; acc[0].y += v.y * w0.x; acc[0].z += v.z * w0.x; acc[0].w += v.w * w0.x;
        acc[1].x += v.x * w0.y; acc[1].y += v.y * w0.y; acc[1].z += v.z * w0.y; acc[1].w += v.w * w0.y;
        acc[2].x += v.x * w0.z; acc[2].y += v.y * w0.z; acc[2].z += v.z * w0.z; acc[2].w += v.w * w0.z;
        acc[3].x += v.x * w0.w; acc[3].y += v.y * w0.w; acc[3].z += v.z * w0.w; acc[3].w += v.w * w0.w;
        acc[4].x += v.x * w1.x; acc[4].y += v.y * w1.x; acc[4].z += v.z * w1.x; acc[4].w += v.w * w1.x;
        acc[5].x += v.x * w1.y; acc[5].y += v.y * w1.y; acc[5].z += v.z * w1.y; acc[5].w += v.w * w1.y;
        acc[6].x += v.x * w1.z; acc[6].y += v.y * w1.z; acc[6].z += v.z * w1.z; acc[6].w += v.w * w1.z;
        acc[7].x += v.x * w1.w; acc[7].y += v.y * w1.w; acc[7].z += v.z * w1.w; acc[7].w += v.w * w1.w;
        acc[8].x += v.x * w8;   acc[8].y += v.y * w8;   acc[8].z += v.z * w8;   acc[8].w += v.w * w8;
    }

    // stage partials: warp w writes its [9][128] slice (conflict-free STS.128)
#pragma unroll
    for (int k = 0; k < 9; k++)
        *(float4*)(s_part + (w * 9 + k) * 128 + lane * 4) = acc[k];
    __syncthreads();

    // reduce over 8 warps + apply seg gate + bias, store d_ti
    for (int i = tid; i < 288; i += 256) {     // 288 = 9 taps * 32 px-quads
        int k = i / 32;
        int q = i - k * 32;
        float4 s = make_float4(0.f, 0.f, 0.f, 0.f);
#pragma unroll
        for (int ww = 0; ww < 8; ww++) {
            float4 t = *(const float4*)(s_part + (ww * 9 + k) * 128 + q * 4);
            s.x += t.x; s.y += t.y; s.z += t.z; s.w += t.w;
        }
        float cb = d_cb[k];
        float4 sg = *(const float4*)(seg + HW + px0 + q * 4);
        float4 o;
        o.x = cb + sg.x * s.x;
        o.y = cb + sg.y * s.y;
        o.z = cb + sg.z * s.z;
        o.w = cb + sg.w * s.w;
        *(float4*)(&d_ti[k][px0 + q * 4]) = o;
    }
}

// ---------------- voxel part: in-smem compaction + gather + REDG -------------
template <int LVL, int C4>
__device__ __forceinline__ void voxel_body(const float* __restrict__ vf,
                                           float* smem, int blk) {
    float4* sw   = (float4*)smem;               // 9*C4 float4
    int2* s_lst  = (int2*)(smem + 2304);        // 256 int2
    int* s_w     = (int*)(smem + 2816);         // 9 ints

    int tid = threadIdx.x;
    const float4* wsrc = (LVL == 0) ? (const float4*)d_G0
                        : (LVL == 1) ? (const float4*)d_G1
                                     : (const float4*)d_Wpt;
    for (int i = tid; i < 9 * C4; i += 256) sw[i] = wsrc[i];

    // local compaction of this block's 256 cells
    int cell = blk * 256 + tid;
    int p = d_win[LVL][cell];
    bool v = p >= 0;
    unsigned m = __ballot_sync(0xffffffffu, v);
    int lane = tid & 31;
    int w    = tid >> 5;
    if (lane == 0) s_w[w] = __popc(m);
    __syncthreads();
    if (tid == 0) {
        int t = 0;
#pragma unroll
        for (int i = 0; i < 8; i++) { int c = s_w[i]; s_w[i] = t; t += c; }
        s_w[8] = t;
    }
    __syncthreads();
    if (v) {
        int pos = s_w[w] + __popc(m & ((1u << lane) - 1));
        s_lst[pos] = make_int2(cell, p);
    }
    __syncthreads();
    int n = s_w[8];

    int sub = lane >> 3;   // slot within warp (0..3)
    int cs  = lane & 7;    // channel lane (0..7)

    for (int base = 0; base < n; base += 64) {
        int i0 = base + w * 8 + sub * 2;
        int i1 = i0 + 1;
        bool ok0 = i0 < n;
        bool ok1 = i1 < n;
        int2 e0 = ok0 ? s_lst[i0] : make_int2(0, 0);
        int2 e1 = ok1 ? s_lst[i1] : make_int2(0, 0);
        const float4* rowA = (const float4*)vf + (size_t)e0.y * C4;
        const float4* rowB = (const float4*)vf + (size_t)e1.y * C4;

        float accA[9], accB[9];
#pragma unroll
        for (int k = 0; k < 9; k++) { accA[k] = 0.f; accB[k] = 0.f; }

#pragma unroll 2
        for (int mm = 0; mm < C4 / 8; mm++) {
            int c4 = cs + 8 * mm;
            float4 va = rowA[c4];
            float4 vb = rowB[c4];
#pragma unroll
            for (int k = 0; k < 9; k++) {
                float4 wv = sw[k * C4 + c4];
                accA[k] += va.x * wv.x + va.y * wv.y + va.z * wv.z + va.w * wv.w;
                accB[k] += vb.x * wv.x + vb.y * wv.y + vb.z * wv.z + vb.w * wv.w;
            }
        }
#pragma unroll
        for (int k = 0; k < 9; k++) {
            float sA = accA[k];
            float sB = accB[k];
            sA += __shfl_xor_sync(0xffffffffu, sA, 1);
            sB += __shfl_xor_sync(0xffffffffu, sB, 1);
            sA += __shfl_xor_sync(0xffffffffu, sA, 2);
            sB += __shfl_xor_sync(0xffffffffu, sB, 2);
            sA += __shfl_xor_sync(0xffffffffu, sA, 4);
            sB += __shfl_xor_sync(0xffffffffu, sB, 4);
            if (cs == 0) {
                if (ok0) atomicAdd(&d_tp[k][e0.x], sA);   // REDG.F32, no return
                if (ok1) atomicAdd(&d_tp[k][e1.x], sB);
            }
        }
    }
}

// ---------------- K2: fused work kernel, 900 vox + 600 img interleaved 3:2 ----
// b%5: {0:vox2, 1:img, 2:vox1, 3:img, 4:vox0}; 1500 blocks total
__global__ void __launch_bounds__(256, 4) k_work(const float* __restrict__ img,
                                                 const float* __restrict__ seg,
                                                 const float* __restrict__ vf0,
                                                 const float* __restrict__ vf1,
                                                 const float* __restrict__ vf2) {
    __shared__ __align__(16) float smem[12288];   // 48KB union (img: 3072+9216)
    int b = blockIdx.x;
    int type = b % 5;
    int g5 = b / 5;                               // 0..299
    if (type == 0)      voxel_body<2, 64>(vf2, smem, g5);
    else if (type == 2) voxel_body<1, 32>(vf1, smem, g5);
    else if (type == 4) voxel_body<0, 16>(vf0, smem, g5);
    else                img_body(img, seg, smem, g5 * 2 + (type == 3));
}

// ---------------- K3: att (128 px into smem) + gated output stream ------------
__global__ void __launch_bounds__(256) k_attout(const float* __restrict__ img,
                                                const float* __restrict__ seg,
                                                const float* __restrict__ sbb,
                                                float* __restrict__ out) {
    __shared__ __align__(16) float satt[128];
    int tid = threadIdx.x;
    int base = blockIdx.x * 128;
    if (tid < 128) {
        int pix = base + tid;
        int y = pix / Ww;
        int x = pix - y * Ww;
        float sum = sbb[0];
#pragma unroll
        for (int ky = 0; ky < 3; ky++) {
            int yy = y + ky - 1;
            if (yy < 0 || yy >= Hh) continue;
#pragma unroll
            for (int kx = 0; kx < 3; kx++) {
                int xx = x + kx - 1;
                if (xx < 0 || xx >= Ww) continue;
                int kk = ky * 3 + kx;
                int ni = yy * Ww + xx;
                sum += d_ti[kk][ni] + d_tp[kk][ni];
            }
        }
        float att = 1.f / (1.f + __expf(-sum));
        satt[tid] = att * seg[HW + pix];
    }
    __syncthreads();

    // stream all 256 channels for this block's 128 pixels (32 float4 per channel)
    int q = tid & 31;          // pixel-quad within block (0..31)
    int c0 = tid >> 5;         // starting channel (0..7)
    float4 a = ((const float4*)satt)[q];
    const float4* im4 = (const float4*)img;
    float4* o4 = (float4*)out;
    size_t idx = (size_t)c0 * (HW / 4) + (base / 4) + q;
#pragma unroll 8
    for (int c = c0; c < 256; c += 8, idx += (size_t)8 * (HW / 4)) {
        float4 v = im4[idx];
        v.x *= a.x; v.y *= a.y; v.z *= a.z; v.w *= a.w;
        o4[idx] = v;
    }
}

extern "C" void kernel_launch(void* const* d_in, const int* in_sizes, int n_in,
                              void* d_out, int out_size) {
    const float* img = (const float*)d_in[0];
    const float* seg = (const float*)d_in[1];

    int iv0, iv1, iv2, ig0, ig1, ig2;
    if (in_sizes[3] == 2 * NP) { iv0 = 2; ig0 = 3; iv1 = 4; ig1 = 5; iv2 = 6; ig2 = 7; }
    else                       { iv0 = 2; iv1 = 3; iv2 = 4; ig0 = 5; ig1 = 6; ig2 = 7; }

    const float* vf0 = (const float*)d_in[iv0];
    const float* vf1 = (const float*)d_in[iv1];
    const float* vf2 = (const float*)d_in[iv2];
    const int*   g0  = (const int*)d_in[ig0];
    const int*   g1  = (const int*)d_in[ig1];
    const int*   g2  = (const int*)d_in[ig2];
    const float* rw0 = (const float*)d_in[8];
    const float* rb0 = (const float*)d_in[9];
    const float* rw1 = (const float*)d_in[10];
    const float* rb1 = (const float*)d_in[11];
    const float* sbw = (const float*)d_in[12];
    const float* sbb = (const float*)d_in[13];

    k_initprep<<<684, 256>>>(rw0, rb0, rw1, rb1, sbw);
    k_scatter<<<(3 * NP + 255) / 256, 256>>>(g0, g1, g2);
    k_work<<<1500, 256>>>(img, seg, vf0, vf1, vf2);
    k_attout<<<HW / 128, 256>>>(img, seg, sbb, (float*)d_out);
}

// round 17
// speedup vs baseline: 1.1029x; 1.0138x over previous
#include <cuda_runtime.h>
#include <math.h>

#define Hh 160
#define Ww 480
#define HW 76800
#define NP 120000

// ---------------- scratch (no allocations allowed) ----------------
__device__ __align__(16) int    d_win[3][HW];
__device__ __align__(16) float4 d_G0[9][16];    // folded red_w0 -> tap weights [k][c/4]
__device__ __align__(16) float4 d_G1[9][32];    // folded red_w1 -> tap weights
__device__ __align__(16) float4 d_Wpt[9][64];   // sb_w[256:512] transposed to [k][o/4]
__device__ __align__(16) float4 d_Wb[768];      // img tap weights, [c][12] padded rows
__device__ float  d_cb[9];                      // folded bias constants per tap
__device__ __align__(16) float  d_ti[9][HW];    // image-part tap maps (incl cb)
__device__ __align__(16) float  d_tp[9][HW];    // voxel tap maps (REDG-accumulated)

// ---------------- K0a: prep folded weights (9 blocks) -------------------------
__global__ void k_prep(const float* __restrict__ rw0, const float* __restrict__ rb0,
                       const float* __restrict__ rw1, const float* __restrict__ rb1,
                       const float* __restrict__ sbw) {
    int k = blockIdx.x;
    int tid = threadIdx.x;
    ((float*)d_Wb)[tid * 12 + k] = sbw[tid * 9 + k];           // img weights, padded rows
    ((float*)d_Wpt)[k * 256 + tid] = sbw[(256 + tid) * 9 + k];
    if (tid < 64) {
        float s = 0.f;
        for (int o = 0; o < 256; o++) s += rw0[o * 64 + tid] * sbw[(256 + o) * 9 + k];
        ((float*)d_G0)[k * 64 + tid] = s;
    }
    if (tid < 128) {
        float s = 0.f;
        for (int o = 0; o < 256; o++) s += rw1[o * 128 + tid] * sbw[(256 + o) * 9 + k];
        ((float*)d_G1)[k * 128 + tid] = s;
    }
    if (tid == 0) {
        float s = 0.f;
        for (int o = 0; o < 256; o++) s += (rb0[o] + rb1[o]) * sbw[(256 + o) * 9 + k];
        d_cb[k] = s;
    }
}

// ---------------- K0b: init d_tp and winner maps (675 blocks) -----------------
__global__ void k_init() {
    int i = blockIdx.x * 256 + threadIdx.x;   // 0 .. 172799 float4 over d_tp
    ((float4*)d_tp)[i] = make_float4(0.f, 0.f, 0.f, 0.f);
    if (i < 3 * HW / 4) ((int4*)d_win)[i] = make_int4(-1, -1, -1, -1);
}

// ---------------- K1: scatter, last-write-wins == max point index ------------
__global__ void k_scatter(const int* __restrict__ g0, const int* __restrict__ g1,
                          const int* __restrict__ g2) {
    int i = blockIdx.x * blockDim.x + threadIdx.x;
    if (i >= 3 * NP) return;
    int lvl = i / NP;
    int p = i - lvl * NP;
    const int* g = (lvl == 0) ? g0 : ((lvl == 1) ? g1 : g2);
    int2 xy = ((const int2*)g)[p];
    if (xy.x >= 0 && xy.x < Ww && xy.y >= 0 && xy.y < Hh)
        atomicMax(&d_win[lvl][xy.y * Ww + xy.x], p);
}

// ---------------- img part: channel-uniform warp layout ----------------------
// warp = 1 channel x 128 px per iter (512B contiguous LDG, broadcast LDS);
// warp w covers channels [32w, 32w+32); cross-warp combine via s_part.
__device__ __forceinline__ void img_body(const float* __restrict__ img,
                                         const float* __restrict__ seg,
                                         float* smem, int blk) {
    float* sWf    = smem;           // 3072 floats: [c][12] padded weight rows
    float* s_part = smem + 3072;    // 8*9*128 floats: per-warp partials

    int tid = threadIdx.x;
    for (int i = tid; i < 768; i += 256) ((float4*)sWf)[i] = d_Wb[i];
    __syncthreads();

    int lane = tid & 31;
    int w    = tid >> 5;
    int px0  = blk * 128;
    int px   = px0 + lane * 4;

    float4 acc[9];
#pragma unroll
    for (int k = 0; k < 9; k++) acc[k] = make_float4(0.f, 0.f, 0.f, 0.f);

#pragma unroll 2
    for (int m = 0; m < 32; m++) {
        int c = w * 32 + m;
        float4 v = *(const float4*)(img + (size_t)c * HW + px);
        const float* wp = sWf + c * 12;
        float4 w0 = *(const float4*)wp;        // broadcast LDS
        float4 w1 = *(const float4*)(wp + 4);
        float  w8 = wp[8];
        acc[0].x += v.x * w0.x; acc[0].y += v.y * w0.x; acc[0].z += v.z * w0.x; acc[0].w += v.w * w0.x;
        acc[1].x += v.x * w0.y; acc[1].y += v.y * w0.y; acc[1].z += v.z * w0.y; acc[1].w += v.w * w0.y;
        acc[2].x += v.x * w0.z; acc[2].y += v.y * w0.z; acc[2].z += v.z * w0.z; acc[2].w += v.w * w0.z;
        acc[3].x += v.x * w0.w; acc[3].y += v.y * w0.w; acc[3].z += v.z * w0.w; acc[3].w += v.w * w0.w;
        acc[4].x += v.x * w1.x; acc[4].y += v.y * w1.x; acc[4].z += v.z * w1.x; acc[4].w += v.w * w1.x;
        acc[5].x += v.x * w1.y; acc[5].y += v.y * w1.y; acc[5].z += v.z * w1.y; acc[5].w += v.w * w1.y;
        acc[6].x += v.x * w1.z; acc[6].y += v.y * w1.z; acc[6].z += v.z * w1.z; acc[6].w += v.w * w1.z;
        acc[7].x += v.x * w1.w; acc[7].y += v.y * w1.w; acc[7].z += v.z * w1.w; acc[7].w += v.w * w1.w;
        acc[8].x += v.x * w8;   acc[8].y += v.y * w8;   acc[8].z += v.z * w8;   acc[8].w += v.w * w8;
    }

    // stage partials: warp w writes its [9][128] slice (conflict-free STS.128)
#pragma unroll
    for (int k = 0; k < 9; k++)
        *(float4*)(s_part + (w * 9 + k) * 128 + lane * 4) = acc[k];
    __syncthreads();

    // reduce over 8 warps + apply seg gate + bias, store d_ti
    for (int i = tid; i < 288; i += 256) {     // 288 = 9 taps * 32 px-quads
        int k = i / 32;
        int q = i - k * 32;
        float4 s = make_float4(0.f, 0.f, 0.f, 0.f);
#pragma unroll
        for (int ww = 0; ww < 8; ww++) {
            float4 t = *(const float4*)(s_part + (ww * 9 + k) * 128 + q * 4);
            s.x += t.x; s.y += t.y; s.z += t.z; s.w += t.w;
        }
        float cb = d_cb[k];
        float4 sg = *(const float4*)(seg + HW + px0 + q * 4);
        float4 o;
        o.x = cb + sg.x * s.x;
        o.y = cb + sg.y * s.y;
        o.z = cb + sg.z * s.z;
        o.w = cb + sg.w * s.w;
        *(float4*)(&d_ti[k][px0 + q * 4]) = o;
    }
}

// ---------------- voxel part: in-smem compaction + gather + REDG -------------
template <int LVL, int C4>
__device__ __forceinline__ void voxel_body(const float* __restrict__ vf,
                                           float* smem, int blk) {
    float4* sw   = (float4*)smem;               // 9*C4 float4
    int2* s_lst  = (int2*)(smem + 2304);        // 256 int2
    int* s_w     = (int*)(smem + 2816);         // 9 ints

    int tid = threadIdx.x;
    const float4* wsrc = (LVL == 0) ? (const float4*)d_G0
                        : (LVL == 1) ? (const float4*)d_G1
                                     : (const float4*)d_Wpt;
    for (int i = tid; i < 9 * C4; i += 256) sw[i] = wsrc[i];

    // local compaction of this block's 256 cells
    int cell = blk * 256 + tid;
    int p = d_win[LVL][cell];
    bool v = p >= 0;
    unsigned m = __ballot_sync(0xffffffffu, v);
    int lane = tid & 31;
    int w    = tid >> 5;
    if (lane == 0) s_w[w] = __popc(m);
    __syncthreads();
    if (tid == 0) {
        int t = 0;
#pragma unroll
        for (int i = 0; i < 8; i++) { int c = s_w[i]; s_w[i] = t; t += c; }
        s_w[8] = t;
    }
    __syncthreads();
    if (v) {
        int pos = s_w[w] + __popc(m & ((1u << lane) - 1));
        s_lst[pos] = make_int2(cell, p);
    }
    __syncthreads();
    int n = s_w[8];

    int sub = lane >> 3;   // slot within warp (0..3)
    int cs  = lane & 7;    // channel lane (0..7)

    for (int base = 0; base < n; base += 64) {
        int i0 = base + w * 8 + sub * 2;
        int i1 = i0 + 1;
        bool ok0 = i0 < n;
        bool ok1 = i1 < n;
        int2 e0 = ok0 ? s_lst[i0] : make_int2(0, 0);
        int2 e1 = ok1 ? s_lst[i1] : make_int2(0, 0);
        const float4* rowA = (const float4*)vf + (size_t)e0.y * C4;
        const float4* rowB = (const float4*)vf + (size_t)e1.y * C4;

        float accA[9], accB[9];
#pragma unroll
        for (int k = 0; k < 9; k++) { accA[k] = 0.f; accB[k] = 0.f; }

#pragma unroll 2
        for (int mm = 0; mm < C4 / 8; mm++) {
            int c4 = cs + 8 * mm;
            float4 va = rowA[c4];
            float4 vb = rowB[c4];
#pragma unroll
            for (int k = 0; k < 9; k++) {
                float4 wv = sw[k * C4 + c4];
                accA[k] += va.x * wv.x + va.y * wv.y + va.z * wv.z + va.w * wv.w;
                accB[k] += vb.x * wv.x + vb.y * wv.y + vb.z * wv.z + vb.w * wv.w;
            }
        }
#pragma unroll
        for (int k = 0; k < 9; k++) {
            float sA = accA[k];
            float sB = accB[k];
            sA += __shfl_xor_sync(0xffffffffu, sA, 1);
            sB += __shfl_xor_sync(0xffffffffu, sB, 1);
            sA += __shfl_xor_sync(0xffffffffu, sA, 2);
            sB += __shfl_xor_sync(0xffffffffu, sB, 2);
            sA += __shfl_xor_sync(0xffffffffu, sA, 4);
            sB += __shfl_xor_sync(0xffffffffu, sB, 4);
            if (cs == 0) {
                if (ok0) atomicAdd(&d_tp[k][e0.x], sA);   // REDG.F32, no return
                if (ok1) atomicAdd(&d_tp[k][e1.x], sB);
            }
        }
    }
}

// ---------------- K2: fused work kernel, 900 vox + 600 img interleaved 3:2 ----
// b%5: {0:vox2, 1:img, 2:vox1, 3:img, 4:vox0}; 1500 blocks total
__global__ void __launch_bounds__(256, 4) k_work(const float* __restrict__ img,
                                                 const float* __restrict__ seg,
                                                 const float* __restrict__ vf0,
                                                 const float* __restrict__ vf1,
                                                 const float* __restrict__ vf2) {
    __shared__ __align__(16) float smem[12288];   // 48KB union (img: 3072+9216)
    int b = blockIdx.x;
    int type = b % 5;
    int g5 = b / 5;                               // 0..299
    if (type == 0)      voxel_body<2, 64>(vf2, smem, g5);
    else if (type == 2) voxel_body<1, 32>(vf1, smem, g5);
    else if (type == 4) voxel_body<0, 16>(vf0, smem, g5);
    else                img_body(img, seg, smem, g5 * 2 + (type == 3));
}

// ---------------- K3: att (128 px into smem) + gated output stream ------------
// 1200 blocks: pair of blocks shares a 128-px group, each streams 128 channels
__global__ void __launch_bounds__(256) k_attout(const float* __restrict__ img,
                                                const float* __restrict__ seg,
                                                const float* __restrict__ sbb,
                                                float* __restrict__ out) {
    __shared__ __align__(16) float satt[128];
    int tid = threadIdx.x;
    int pg   = blockIdx.x >> 1;      // pixel group (0..599)
    int half = blockIdx.x & 1;       // channel half
    int base = pg * 128;
    if (tid < 128) {
        int pix = base + tid;
        int y = pix / Ww;
        int x = pix - y * Ww;
        float sum = sbb[0];
#pragma unroll
        for (int ky = 0; ky < 3; ky++) {
            int yy = y + ky - 1;
            if (yy < 0 || yy >= Hh) continue;
#pragma unroll
            for (int kx = 0; kx < 3; kx++) {
                int xx = x + kx - 1;
                if (xx < 0 || xx >= Ww) continue;
                int kk = ky * 3 + kx;
                int ni = yy * Ww + xx;
                sum += d_ti[kk][ni] + d_tp[kk][ni];
            }
        }
        float att = 1.f / (1.f + __expf(-sum));
        satt[tid] = att * seg[HW + pix];
    }
    __syncthreads();

    // stream 128 channels for this block's 128 pixels (32 float4 per channel)
    int q = tid & 31;                    // pixel-quad within block (0..31)
    int c0 = half * 128 + (tid >> 5);    // starting channel
    int cend = half * 128 + 128;
    float4 a = ((const float4*)satt)[q];
    const float4* im4 = (const float4*)img;
    float4* o4 = (float4*)out;
    size_t idx = (size_t)c0 * (HW / 4) + (base / 4) + q;
#pragma unroll 8
    for (int c = c0; c < cend; c += 8, idx += (size_t)8 * (HW / 4)) {
        float4 v = im4[idx];
        v.x *= a.x; v.y *= a.y; v.z *= a.z; v.w *= a.w;
        o4[idx] = v;
    }
}

extern "C" void kernel_launch(void* const* d_in, const int* in_sizes, int n_in,
                              void* d_out, int out_size) {
    const float* img = (const float*)d_in[0];
    const float* seg = (const float*)d_in[1];

    int iv0, iv1, iv2, ig0, ig1, ig2;
    if (in_sizes[3] == 2 * NP) { iv0 = 2; ig0 = 3; iv1 = 4; ig1 = 5; iv2 = 6; ig2 = 7; }
    else                       { iv0 = 2; iv1 = 3; iv2 = 4; ig0 = 5; ig1 = 6; ig2 = 7; }

    const float* vf0 = (const float*)d_in[iv0];
    const float* vf1 = (const float*)d_in[iv1];
    const float* vf2 = (const float*)d_in[iv2];
    const int*   g0  = (const int*)d_in[ig0];
    const int*   g1  = (const int*)d_in[ig1];
    const int*   g2  = (const int*)d_in[ig2];
    const float* rw0 = (const float*)d_in[8];
    const float* rb0 = (const float*)d_in[9];
    const float* rw1 = (const float*)d_in[10];
    const float* rb1 = (const float*)d_in[11];
    const float* sbw = (const float*)d_in[12];
    const float* sbb = (const float*)d_in[13];

    k_prep<<<9, 256>>>(rw0, rb0, rw1, rb1, sbw);
    k_init<<<675, 256>>>();
    k_scatter<<<(3 * NP + 255) / 256, 256>>>(g0, g1, g2);
    k_work<<<1500, 256>>>(img, seg, vf0, vf1, vf2);
    k_attout<<<1200, 256>>>(img, seg, sbb, (float*)d_out);
}